// round 9
// baseline (speedup 1.0000x reference)
#include <cuda_runtime.h>
#include <math.h>

// 9x9 max-dilation, SAME padding with -inf border. Fully warp-autonomous:
// no smem, no __syncthreads. 8 cols/thread (two float4), two 4-row
// Gil-Werman chunks per block.
//   - block = 1024 (full width) x 8 output rows; 4 warps x 32 lanes x 8 cols
//   - vertical 9-max in registers per chunk (suffix over 8 rows + streamed
//     prefix over 4 more)
//   - horizontal 9-max: 8-wide prefix/suffix + 8 shuffles per row; warp-edge
//     halo (4 cols) recomputed locally by lanes 0 and 31 from one extra
//     guarded float4 column (no cross-warp communication at all)
//   - interior strips (1..126) use an unpredicated row fast path
// Input 16x1024x1024x1 fp32.

#define IMG 1024
#define TH 8              // output rows per block
#define CH 4              // output rows per chunk
#define NTH 128
#define NW 4              // warps per block (4 x 256 cols = 1024)

__device__ __forceinline__ float4 max4(float4 a, float4 b) {
    return make_float4(fmaxf(a.x, b.x), fmaxf(a.y, b.y),
                       fmaxf(a.z, b.z), fmaxf(a.w, b.w));
}

#define NEGF4 make_float4(-INFINITY, -INFINITY, -INFINITY, -INFINITY)

template<bool GUARD>
__device__ __forceinline__ float4 ldrow(const float* __restrict__ img, int gy, int gx) {
    if (GUARD && (unsigned)gy >= (unsigned)IMG) return NEGF4;
    return *(const float4*)(img + (size_t)gy * IMG + gx);
}

template<bool GUARD>
__device__ __forceinline__ void process_strip(
    const float* __restrict__ img, float* __restrict__ oimg,
    int strip, int lane, int w)
{
    const int gx = w * 256 + lane * 8;    // first of this thread's 8 cols
    const bool edge = (lane == 0) || (lane == 31);
    const int gxh = (lane == 0) ? gx - 4 : gx + 8;            // halo column start
    const bool hval = edge && ((unsigned)gxh < (unsigned)IMG); // image-border check

    #pragma unroll
    for (int c = 0; c < 2; c++) {
        const int base = strip * TH + c * CH - 4;   // first raw row of chunk

        // ---- vertical: suffix maxes over raw rows base..base+7 (a|b halves) ----
        float4 ra[8], rb[8];
        #pragma unroll
        for (int j = 0; j < 8; j++) {
            ra[j] = ldrow<GUARD>(img, base + j, gx);
            rb[j] = ldrow<GUARD>(img, base + j, gx + 4);
        }
        const float4 ma47 = max4(max4(ra[4], ra[5]), max4(ra[6], ra[7]));
        const float4 Sa3 = max4(ra[3], ma47);
        const float4 Sa2 = max4(ra[2], Sa3);
        const float4 Sa1 = max4(ra[1], Sa2);
        const float4 Sa0 = max4(ra[0], Sa1);
        const float4 mb47 = max4(max4(rb[4], rb[5]), max4(rb[6], rb[7]));
        const float4 Sb3 = max4(rb[3], mb47);
        const float4 Sb2 = max4(rb[2], Sb3);
        const float4 Sb1 = max4(rb[1], Sb2);
        const float4 Sb0 = max4(rb[0], Sb1);

        // ---- vertical: streamed prefix over raw rows base+8..base+11 ----
        float4 vma[CH], vmb[CH];
        {
            float4 qa = ldrow<GUARD>(img, base + 8, gx);
            float4 qb = ldrow<GUARD>(img, base + 8, gx + 4);
            vma[0] = max4(Sa0, qa);  vmb[0] = max4(Sb0, qb);
            float4 na = ldrow<GUARD>(img, base + 9, gx);
            float4 nb = ldrow<GUARD>(img, base + 9, gx + 4);
            qa = max4(qa, na);  qb = max4(qb, nb);
            vma[1] = max4(Sa1, qa);  vmb[1] = max4(Sb1, qb);
            na = ldrow<GUARD>(img, base + 10, gx);
            nb = ldrow<GUARD>(img, base + 10, gx + 4);
            qa = max4(qa, na);  qb = max4(qb, nb);
            vma[2] = max4(Sa2, qa);  vmb[2] = max4(Sb2, qb);
            na = ldrow<GUARD>(img, base + 11, gx);
            nb = ldrow<GUARD>(img, base + 11, gx + 4);
            qa = max4(qa, na);  qb = max4(qb, nb);
            vma[3] = max4(Sa3, qa);  vmb[3] = max4(Sb3, qb);
        }

        // ---- edge lanes: recompute the 4-col halo's vertical 9-max locally ----
        float4 hvm[CH];
        if (edge) {
            float4 h[8];
            #pragma unroll
            for (int j = 0; j < 8; j++)
                h[j] = hval ? ldrow<GUARD>(img, base + j, gxh) : NEGF4;
            const float4 hm47 = max4(max4(h[4], h[5]), max4(h[6], h[7]));
            const float4 hS3 = max4(h[3], hm47);
            const float4 hS2 = max4(h[2], hS3);
            const float4 hS1 = max4(h[1], hS2);
            const float4 hS0 = max4(h[0], hS1);
            float4 q = hval ? ldrow<GUARD>(img, base + 8, gxh) : NEGF4;
            hvm[0] = max4(hS0, q);
            float4 n = hval ? ldrow<GUARD>(img, base + 9, gxh) : NEGF4;
            q = max4(q, n);  hvm[1] = max4(hS1, q);
            n = hval ? ldrow<GUARD>(img, base + 10, gxh) : NEGF4;
            q = max4(q, n);  hvm[2] = max4(hS2, q);
            n = hval ? ldrow<GUARD>(img, base + 11, gxh) : NEGF4;
            q = max4(q, n);  hvm[3] = max4(hS3, q);
        }

        // ---- horizontal 9-max: 8-wide prefix/suffix + 8 shuffles ----
        #pragma unroll
        for (int t = 0; t < CH; t++) {
            const float4 a = vma[t];
            const float4 b = vmb[t];
            const float p0 = a.x;
            const float p1 = fmaxf(p0, a.y);
            const float p2 = fmaxf(p1, a.z);
            const float p3 = fmaxf(p2, a.w);
            const float p4 = fmaxf(p3, b.x);
            const float p5 = fmaxf(p4, b.y);
            const float p6 = fmaxf(p5, b.z);
            const float p7 = fmaxf(p6, b.w);
            const float s7 = b.w;
            const float s6 = fmaxf(b.z, s7);
            const float s5 = fmaxf(b.y, s6);
            const float s4 = fmaxf(b.x, s5);
            const float s3 = fmaxf(a.w, s4);
            const float s2 = fmaxf(a.z, s3);
            const float s1 = fmaxf(a.y, s2);
            const float s0 = p7;

            float sU4 = __shfl_up_sync(0xffffffffu, s4, 1);
            float sU5 = __shfl_up_sync(0xffffffffu, s5, 1);
            float sU6 = __shfl_up_sync(0xffffffffu, s6, 1);
            float sU7 = __shfl_up_sync(0xffffffffu, s7, 1);
            float pD0 = __shfl_down_sync(0xffffffffu, p0, 1);
            float pD1 = __shfl_down_sync(0xffffffffu, p1, 1);
            float pD2 = __shfl_down_sync(0xffffffffu, p2, 1);
            float pD3 = __shfl_down_sync(0xffffffffu, p3, 1);

            if (lane == 0) {   // left halo cols gx-4..gx-1 (locally computed)
                sU7 = hvm[t].w;
                sU6 = fmaxf(hvm[t].z, sU7);
                sU5 = fmaxf(hvm[t].y, sU6);
                sU4 = fmaxf(hvm[t].x, sU5);
            }
            if (lane == 31) {  // right halo cols gx+8..gx+11 (locally computed)
                pD0 = hvm[t].x;
                pD1 = fmaxf(pD0, hvm[t].y);
                pD2 = fmaxf(pD1, hvm[t].z);
                pD3 = fmaxf(pD2, hvm[t].w);
            }

            float4 oa, ob;
            oa.x = fmaxf(sU4, p4);
            oa.y = fmaxf(sU5, p5);
            oa.z = fmaxf(sU6, p6);
            oa.w = fmaxf(sU7, p7);
            ob.x = fmaxf(s0, pD0);
            ob.y = fmaxf(s1, pD1);
            ob.z = fmaxf(s2, pD2);
            ob.w = fmaxf(s3, pD3);

            float* orow = oimg + (size_t)(strip * TH + c * CH + t) * IMG + gx;
            *(float4*)orow = oa;
            *(float4*)(orow + 4) = ob;
        }
    }
}

__global__ __launch_bounds__(NTH)
void dilate9_kernel(const float* __restrict__ in, float* __restrict__ out) {
    const int strip = blockIdx.x;     // 0..127 (8-row strips)
    const int bz    = blockIdx.y;     // batch
    const int tid   = threadIdx.x;
    const int lane  = tid & 31;
    const int w     = tid >> 5;

    const float* img = in  + (size_t)bz * IMG * IMG;
    float*      oimg = out + (size_t)bz * IMG * IMG;

    // strips 1..126: raw rows [strip*8-4, strip*8+11] all within [0,1024)
    if (strip >= 1 && strip <= 126)
        process_strip<false>(img, oimg, strip, lane, w);
    else
        process_strip<true>(img, oimg, strip, lane, w);
}

extern "C" void kernel_launch(void* const* d_in, const int* in_sizes, int n_in,
                              void* d_out, int out_size) {
    const float* in = (const float*)d_in[0];
    float* out = (float*)d_out;
    const int batch = in_sizes[0] / (IMG * IMG);
    dim3 grid(IMG / TH, batch);
    dilate9_kernel<<<grid, NTH>>>(in, out);
}